// round 3
// baseline (speedup 1.0000x reference)
#include <cuda_runtime.h>
#include <stdint.h>

// QuantEmbedding: out = gather(QIL_quantize(W, p, c), x), plus scalars s and p.
// Fused: quantize only the gathered rows (100 MB traffic instead of 408 MB).
//
// Reference math (JAX):
//   p  = max(pruning_point, 0); c = clipping_point; s = 127/(c-p)
//   wq = |w| < p ? 0 : (|w|-p)*s*sign(w)
//   wq = round(clip(wq, -127, 127))          (round half-to-even == rintf)
//   out = (|wq|/s + p) * sign(wq)            (note: wq==0 -> out 0, not ±p)

__device__ __forceinline__ float qil_one(float w, float p, float s, float inv_s) {
    float aw = fabsf(w);
    if (aw < p) return 0.0f;
    float q = rintf(fminf((aw - p) * s, 127.0f));   // q >= 0
    if (q == 0.0f) return 0.0f;                      // sign(wq)==0 case
    return copysignf(fmaf(q, inv_s, p), w);          // (q/s + p) * sign(w)
}

__global__ void qembed_gather_kernel(const int* __restrict__ x,
                                     const float4* __restrict__ w4,
                                     const float* __restrict__ pp,
                                     const float* __restrict__ cp,
                                     float4* __restrict__ out4,
                                     int dim4) {
    const int row = blockIdx.x;
    const int tok = __ldg(&x[row]);

    const float p = fmaxf(pp[0], 0.0f);
    const float c = cp[0];
    const float s = 127.0f / (c - p);
    const float inv_s = 1.0f / s;

    const long long src_base = (long long)tok * dim4;
    const long long dst_base = (long long)row * dim4;

    for (int j = threadIdx.x; j < dim4; j += blockDim.x) {
        float4 v = w4[src_base + j];
        float4 r;
        r.x = qil_one(v.x, p, s, inv_s);
        r.y = qil_one(v.y, p, s, inv_s);
        r.z = qil_one(v.z, p, s, inv_s);
        r.w = qil_one(v.w, p, s, inv_s);
        out4[dst_base + j] = r;
    }
}

// Epilogue: write weight_scaling_factor and p after the embed block.
__global__ void qembed_scalars_kernel(const float* __restrict__ pp,
                                      const float* __restrict__ cp,
                                      float* __restrict__ out,
                                      long long base, int n_scalars) {
    const float p = fmaxf(pp[0], 0.0f);
    const float c = cp[0];
    const float s = 127.0f / (c - p);
    if (n_scalars >= 1) out[base + 0] = s;
    if (n_scalars >= 2) out[base + 1] = p;
}

extern "C" void kernel_launch(void* const* d_in, const int* in_sizes, int n_in,
                              void* d_out, int out_size) {
    const int*   x  = (const int*)d_in[0];          // [batch*seq] int32 token ids
    const float* w  = (const float*)d_in[1];        // [vocab, dim] float32
    const float* pp = (const float*)d_in[2];        // [1]
    const float* cp = (const float*)d_in[3];        // [1]
    float* out = (float*)d_out;

    const int rows = in_sizes[0];                   // batch*seq = 16384

    // Derive dim and scalar-tail layout from out_size.
    long long dim;
    int n_scalars;
    long long osz = (long long)out_size;
    if (rows > 0 && (osz - 2) > 0 && (osz - 2) % rows == 0) {
        dim = (osz - 2) / rows;   n_scalars = 2;    // embed + s + p (expected: 768, 2)
    } else if (rows > 0 && (osz - 1) > 0 && (osz - 1) % rows == 0) {
        dim = (osz - 1) / rows;   n_scalars = 1;
    } else {
        dim = (rows > 0) ? osz / rows : 0;  n_scalars = 0;
    }

    const int dim4 = (int)(dim / 4);                // dim=768 -> 192 float4 per row
    int threads = dim4;
    if (threads > 1024) threads = 1024;
    if (threads < 32)   threads = 32;

    qembed_gather_kernel<<<rows, threads>>>(
        x, (const float4*)w, pp, cp, (float4*)d_out, dim4);

    if (n_scalars > 0) {
        qembed_scalars_kernel<<<1, 1>>>(pp, cp, out, (long long)rows * dim, n_scalars);
    }
}

// round 4
// speedup vs baseline: 1.1574x; 1.1574x over previous
#include <cuda_runtime.h>
#include <stdint.h>

// QuantEmbedding fused: out[0:rows*dim] = gather(QIL_quantize(W,p,c), x),
// out[rows*dim] = s, out[rows*dim+1] = p.  Single kernel, streaming hints.
//
// Reference math (JAX):
//   p  = max(pruning_point, 0); c = clipping_point; s = 127/(c-p)
//   wq = round(clip((|w|-p)*s*sign(w) with |w|<p -> 0, -127, 127))   (rintf)
//   out = (|wq|/s + p)*sign(wq)    (wq==0 -> 0, not ±p)

__device__ __forceinline__ float qil_one(float w, float p, float s, float inv_s) {
    float aw = fabsf(w);
    if (aw < p) return 0.0f;
    float q = rintf(fminf((aw - p) * s, 127.0f));   // q >= 0
    if (q == 0.0f) return 0.0f;                      // sign(wq)==0 case
    return copysignf(fmaf(q, inv_s, p), w);          // (q/s + p)*sign(w)
}

__global__ __launch_bounds__(192)
void qembed_fused_kernel(const int* __restrict__ x,
                         const float4* __restrict__ w4,
                         const float* __restrict__ pp,
                         const float* __restrict__ cp,
                         float4* __restrict__ out4,
                         int dim4, long long scalar_base, int n_scalars) {
    const int row = blockIdx.x;
    const int tok = __ldg(&x[row]);

    const float p = fmaxf(__ldg(&pp[0]), 0.0f);
    const float c = __ldg(&cp[0]);
    const float s = 127.0f / (c - p);
    const float inv_s = 1.0f / s;

    const long long src_base = (long long)tok * dim4;
    const long long dst_base = (long long)row * dim4;

    for (int j = threadIdx.x; j < dim4; j += blockDim.x) {
        float4 v = __ldcs(&w4[src_base + j]);        // evict-first: single-use stream
        float4 r;
        r.x = qil_one(v.x, p, s, inv_s);
        r.y = qil_one(v.y, p, s, inv_s);
        r.z = qil_one(v.z, p, s, inv_s);
        r.w = qil_one(v.w, p, s, inv_s);
        __stcs(&out4[dst_base + j], r);              // streaming store
    }

    // Fused epilogue: scalar tail written by one thread of block 0.
    if (blockIdx.x == 0 && threadIdx.x == 0 && n_scalars > 0) {
        float* out = (float*)out4;
        out[scalar_base] = s;
        if (n_scalars >= 2) out[scalar_base + 1] = p;
    }
}

extern "C" void kernel_launch(void* const* d_in, const int* in_sizes, int n_in,
                              void* d_out, int out_size) {
    const int*   x  = (const int*)d_in[0];          // [batch*seq] token ids
    const float* w  = (const float*)d_in[1];        // [vocab, dim] float32
    const float* pp = (const float*)d_in[2];        // [1]
    const float* cp = (const float*)d_in[3];        // [1]

    const int rows = in_sizes[0];                   // 16384

    // Derive dim and scalar-tail count from out_size.
    long long dim;
    int n_scalars;
    long long osz = (long long)out_size;
    if (rows > 0 && (osz - 2) > 0 && (osz - 2) % rows == 0) {
        dim = (osz - 2) / rows;  n_scalars = 2;     // expected: 768, 2
    } else if (rows > 0 && (osz - 1) > 0 && (osz - 1) % rows == 0) {
        dim = (osz - 1) / rows;  n_scalars = 1;
    } else {
        dim = (rows > 0) ? osz / rows : 0;  n_scalars = 0;
    }

    const int dim4 = (int)(dim / 4);                // 768 -> 192
    int threads = dim4;
    if (threads > 1024) threads = 1024;
    if (threads < 32)   threads = 32;

    qembed_fused_kernel<<<rows, threads>>>(
        x, (const float4*)w, pp, cp, (float4*)d_out,
        dim4, (long long)rows * dim, n_scalars);
}